// round 10
// baseline (speedup 1.0000x reference)
#include <cuda_runtime.h>
#include <cstddef>

// Problem constants
#define BB 512   // batch
#define TT 512   // timesteps
#define FF 64    // input features
#define H1 128   // layer1 hidden
#define G1 512   // 4*H1
#define H2 64    // layer2 hidden
#define G2 256   // 4*H2

typedef unsigned long long u64;

// ---------------------------------------------------------------------------
// Packed fp32x2 helpers (sm_103a): 2 IEEE fp32 FMAs per instruction.
// ---------------------------------------------------------------------------
__device__ __forceinline__ u64 pack2(float lo, float hi) {
    u64 r; asm("mov.b64 %0, {%1, %2};" : "=l"(r) : "f"(lo), "f"(hi)); return r;
}
__device__ __forceinline__ float2 unpack2(u64 v) {
    float2 f; asm("mov.b64 {%0, %1}, %2;" : "=f"(f.x), "=f"(f.y) : "l"(v)); return f;
}
__device__ __forceinline__ void fma2(u64& d, u64 a, u64 b) {
    asm("fma.rn.f32x2 %0, %1, %2, %0;" : "+l"(d) : "l"(a), "l"(b));
}
__device__ __forceinline__ void add2(u64& d, u64 a) {
    asm("add.rn.f32x2 %0, %0, %1;" : "+l"(d) : "l"(a));
}

// ---------------------------------------------------------------------------
// Device scratch
// ---------------------------------------------------------------------------
__device__ float g_Wp1[FF * G1];        // W1 permuted: [f][j*4+gate]
__device__ float g_bp1[G1];
__device__ float g_Up1[H1 * G1];        // U1 permuted: [k][j*4+gate]
__device__ float g_Wp2[H1 * G2];
__device__ float g_bp2[G2];
__device__ float g_Up2[H2 * G2];
__device__ float g_xw1[(size_t)TT * BB * G1];  // [t][b][j*4+gate]
__device__ float g_h1[(size_t)TT * BB * H1];   // [t][b][j]
__device__ float g_xw2[(size_t)TT * BB * G2];  // [t][b][j*4+gate]
__device__ float g_h2[BB * H2];                // final layer2 h

__device__ __forceinline__ float sigf(float x) {
    return __fdividef(1.0f, 1.0f + __expf(-x));
}

// ---------------------------------------------------------------------------
// Prep: permute weights so column n = j*4 + gate  (gate order i,f,g,o)
// ---------------------------------------------------------------------------
__global__ void prep_kernel(const float* __restrict__ W1, const float* __restrict__ U1,
                            const float* __restrict__ b1, const float* __restrict__ W2,
                            const float* __restrict__ U2, const float* __restrict__ b2)
{
    int i = blockIdx.x * blockDim.x + threadIdx.x;
    if (i < FF * G1) {
        int f = i >> 9, n = i & 511;
        int j = n >> 2, gi = n & 3;
        g_Wp1[i] = W1[f * G1 + gi * H1 + j];
    }
    if (i < G1) {
        int j = i >> 2, gi = i & 3;
        g_bp1[i] = b1[gi * H1 + j];
    }
    if (i < H1 * G1) {
        int k = i >> 9, n = i & 511;
        int j = n >> 2, gi = n & 3;
        g_Up1[i] = U1[k * G1 + gi * H1 + j];
    }
    if (i < H1 * G2) {
        int k = i >> 8, n = i & 255;
        int j = n >> 2, gi = n & 3;
        g_Wp2[i] = W2[k * G2 + gi * H2 + j];
    }
    if (i < G2) {
        int j = i >> 2, gi = i & 3;
        g_bp2[i] = b2[gi * H2 + j];
    }
    if (i < H2 * G2) {
        int k = i >> 8, n = i & 255;
        int j = n >> 2, gi = n & 3;
        g_Up2[i] = U2[k * G2 + gi * H2 + j];
    }
}

// ---------------------------------------------------------------------------
// FMA2 GEMM (proven R4):  C[m][n] = sum_k A_row(m)[k] * W[k][n] + bias[n]
// CTA tile 128(m) x 128(n), 256 threads, 2 CTAs/SM.
// ---------------------------------------------------------------------------
#define AS_LD 132
#define GEMM_SMEM ((32 * AS_LD + 32 * 256) * 4)   // 49664 B

__global__ __launch_bounds__(256, 2) void gemm_kernel(
    const float* __restrict__ A, const float* __restrict__ W,
    const float* __restrict__ bias, float* __restrict__ C,
    int sT, int sB, int K, int N)
{
    extern __shared__ float sm[];
    float* As = sm;                  // [32][AS_LD]  k-major, m natural
    float* Wd = sm + 32 * AS_LD;     // [32][4][16][4]: dup pairs, swizzled by tx
    const int tid = threadIdx.x;
    const int tx = tid & 15;
    const int ty = tid >> 4;
    const int mt = blockIdx.x * 128;
    const int nt = blockIdx.y * 128;

    u64 acc[4][8];
#pragma unroll
    for (int p = 0; p < 4; p++)
#pragma unroll
        for (int q = 0; q < 8; q++) acc[p][q] = 0ull;

    const int am = tid & 127;
    const int kc = tid >> 7;
    const int gm0 = mt + am;
    const int t0 = gm0 >> 9, b0 = gm0 & 511;
    const float* arow = A + (size_t)t0 * sT + (size_t)b0 * sB + (kc << 4);

    for (int kt = 0; kt < K; kt += 32) {
#pragma unroll
        for (int kq = 0; kq < 4; kq++) {
            float4 v = *(const float4*)(arow + kt + (kq << 2));
            int kk = (kc << 4) + (kq << 2);
            As[(kk + 0) * AS_LD + am] = v.x;
            As[(kk + 1) * AS_LD + am] = v.y;
            As[(kk + 2) * AS_LD + am] = v.z;
            As[(kk + 3) * AS_LD + am] = v.w;
        }
        {
            int txw = tid & 15;
            int c   = (tid >> 4) & 3;
            int kb  = tid >> 6;
#pragma unroll
            for (int i = 0; i < 8; i++) {
                int k = kb + (i << 2);
                float2 w2 = *(const float2*)(W + (size_t)(kt + k) * N + nt + (txw << 3) + (c << 1));
                *(float4*)(Wd + (k << 8) + (c << 6) + (txw << 2)) =
                    make_float4(w2.x, w2.x, w2.y, w2.y);
            }
        }
        __syncthreads();
#pragma unroll 4
        for (int k = 0; k < 32; k++) {
            const float* ar = As + k * AS_LD + (ty << 3);
            ulonglong2 a01 = *(const ulonglong2*)(ar);
            ulonglong2 a23 = *(const ulonglong2*)(ar + 4);
            const float* wr = Wd + (k << 8) + (tx << 2);
            ulonglong2 w01 = *(const ulonglong2*)(wr);
            ulonglong2 w23 = *(const ulonglong2*)(wr + 64);
            ulonglong2 w45 = *(const ulonglong2*)(wr + 128);
            ulonglong2 w67 = *(const ulonglong2*)(wr + 192);
            u64 av[4] = {a01.x, a01.y, a23.x, a23.y};
            u64 wv[8] = {w01.x, w01.y, w23.x, w23.y, w45.x, w45.y, w67.x, w67.y};
#pragma unroll
            for (int p = 0; p < 4; p++)
#pragma unroll
                for (int q = 0; q < 8; q++) fma2(acc[p][q], av[p], wv[q]);
        }
        __syncthreads();
    }

    u64 bd[8];
#pragma unroll
    for (int q = 0; q < 8; q++) {
        float bv = bias[nt + (tx << 3) + q];
        bd[q] = pack2(bv, bv);
    }
#pragma unroll
    for (int p = 0; p < 4; p++) {
        float2 f[8];
#pragma unroll
        for (int q = 0; q < 8; q++) {
            add2(acc[p][q], bd[q]);
            f[q] = unpack2(acc[p][q]);
        }
        int m0 = mt + (ty << 3) + (p << 1);
        float* c0 = C + (size_t)m0 * N + nt + (tx << 3);
        float* c1 = c0 + N;
        *(float4*)(c0)     = make_float4(f[0].x, f[1].x, f[2].x, f[3].x);
        *(float4*)(c0 + 4) = make_float4(f[4].x, f[5].x, f[6].x, f[7].x);
        *(float4*)(c1)     = make_float4(f[0].y, f[1].y, f[2].y, f[3].y);
        *(float4*)(c1 + 4) = make_float4(f[4].y, f[5].y, f[6].y, f[7].y);
    }
}

// ---------------------------------------------------------------------------
// Layer-1 recurrence, single barrier per step. 128 CTAs x 256 threads.
// thread = (j in [0,128), bh in {0,1}); full K=128 reduction for 2 batch rows.
// U: rows 0..103 in smem, 104..127 in regs. h as dup pairs {h,h} in smem:
// hd[buf][row r][8] = {b0,b0,b1,b1,b2,b2,b3,b3}; thread reads its bh-half.
// Per step: 512 fma2/thread, ONE __syncthreads, no partials exchange.
// ---------------------------------------------------------------------------
#define REC1_SMEM ((104 * 512 + 2 * 1024) * 4)  // 221184 B

__global__ __launch_bounds__(256, 1) void rec1_kernel()
{
    extern __shared__ float sm[];
    float* Us = sm;               // [104][512]
    float* hd = sm + 104 * 512;   // [2][128][8]

    const int tid = threadIdx.x, w = tid >> 5, l = tid & 31;
    const int j = (w << 4) | (l & 15);
    const int bh = l >> 4;
    const int brow = (blockIdx.x << 2) + (bh << 1);

    for (int i = tid; i < 104 * 128; i += 256) {
        int s = i >> 7, c = (i & 127) << 2;
        *(float4*)(Us + s * 512 + c) = *(const float4*)(g_Up1 + s * 512 + c);
    }
    ulonglong2 uw[24];
#pragma unroll
    for (int r = 0; r < 24; r++)
        uw[r] = *(const ulonglong2*)(g_Up1 + (104 + r) * 512 + (j << 2));
    for (int i = tid; i < 2048; i += 256) hd[i] = 0.f;
    float cc0 = 0.f, cc1 = 0.f;
    __syncthreads();

    const float* ucol = Us + (j << 2);
    int buf = 0;
    for (int t = 0; t < TT; t++) {
        u64 z00 = 0, z01 = 0, z10 = 0, z11 = 0;
        ulonglong2 xv0 = *(const ulonglong2*)(g_xw1 + ((size_t)(t * BB + brow) << 9) + (j << 2));
        ulonglong2 xv1 = *(const ulonglong2*)(g_xw1 + ((size_t)(t * BB + brow + 1) << 9) + (j << 2));
        const float* hb = hd + buf * 1024 + (bh << 2);
        const float* up = ucol;
#pragma unroll 4
        for (int r = 0; r < 104; r++) {
            ulonglong2 h2 = *(const ulonglong2*)(hb + (r << 3));   // {hb0,hb0},{hb1,hb1}
            ulonglong2 uv = *(const ulonglong2*)(up);              // {Ui,Uf},{Ug,Uo}
            up += 512;
            fma2(z00, h2.x, uv.x); fma2(z01, h2.x, uv.y);
            fma2(z10, h2.y, uv.x); fma2(z11, h2.y, uv.y);
        }
#pragma unroll
        for (int r = 0; r < 24; r++) {
            ulonglong2 h2 = *(const ulonglong2*)(hb + ((104 + r) << 3));
            fma2(z00, h2.x, uw[r].x); fma2(z01, h2.x, uw[r].y);
            fma2(z10, h2.y, uw[r].x); fma2(z11, h2.y, uw[r].y);
        }
        add2(z00, xv0.x); add2(z01, xv0.y);
        add2(z10, xv1.x); add2(z11, xv1.y);
        float2 p00 = unpack2(z00), p01 = unpack2(z01);
        float2 p10 = unpack2(z10), p11 = unpack2(z11);
        float i0 = sigf(p00.x), f0 = sigf(p00.y), gg0 = fmaxf(p01.x, 0.f), o0 = sigf(p01.y);
        cc0 = f0 * cc0 + i0 * gg0;
        float hv0 = o0 * fmaxf(cc0, 0.f);
        float i1 = sigf(p10.x), f1 = sigf(p10.y), gg1 = fmaxf(p11.x, 0.f), o1 = sigf(p11.y);
        cc1 = f1 * cc1 + i1 * gg1;
        float hv1 = o1 * fmaxf(cc1, 0.f);
        g_h1[((size_t)(t * BB + brow) << 7) + j] = hv0;
        g_h1[((size_t)(t * BB + brow + 1) << 7) + j] = hv1;
        float* hn = hd + (buf ^ 1) * 1024;
        *(ulonglong2*)(hn + (j << 3) + (bh << 2)) =
            make_ulonglong2(pack2(hv0, hv0), pack2(hv1, hv1));
        __syncthreads();
        buf ^= 1;
    }
}

// ---------------------------------------------------------------------------
// Layer-2 recurrence, single barrier per step. 128 CTAs x 256 threads.
// thread = (j in [0,64), b in [0,4)); full K=64 reduction, U2 all in smem.
// ---------------------------------------------------------------------------
#define REC2_SMEM ((64 * 256 + 2 * 512) * 4)  // 69632 B

__global__ __launch_bounds__(256, 1) void rec2_kernel()
{
    extern __shared__ float sm[];
    float* Us = sm;              // [64][256]
    float* hd = sm + 64 * 256;   // [2][64][8] = {b0,b0,b1,b1,b2,b2,b3,b3}

    const int tid = threadIdx.x, w = tid >> 5, l = tid & 31;
    const int j = (w << 3) | (l & 7);
    const int b = l >> 3;
    const int brow = (blockIdx.x << 2) + b;

    for (int i = tid; i < 64 * 64; i += 256) {
        int s = i >> 6, c = (i & 63) << 2;
        *(float4*)(Us + s * 256 + c) = *(const float4*)(g_Up2 + s * 256 + c);
    }
    for (int i = tid; i < 1024; i += 256) hd[i] = 0.f;
    float cc = 0.f;
    __syncthreads();

    const float* ucol = Us + (j << 2);
    int buf = 0;
    for (int t = 0; t < TT; t++) {
        u64 z0 = 0, z1 = 0;
        ulonglong2 xv = *(const ulonglong2*)(g_xw2 + ((size_t)(t * BB + brow) << 8) + (j << 2));
        const float* hb = hd + buf * 512 + (b << 1);
        const float* up = ucol;
#pragma unroll 8
        for (int r = 0; r < 64; r++) {
            u64 h2 = *(const u64*)(hb + (r << 3));   // {h_r[b], h_r[b]}
            ulonglong2 uv = *(const ulonglong2*)(up);
            up += 256;
            fma2(z0, h2, uv.x);
            fma2(z1, h2, uv.y);
        }
        add2(z0, xv.x); add2(z1, xv.y);
        float2 p0 = unpack2(z0), p1 = unpack2(z1);
        float ig = sigf(p0.x), fg = sigf(p0.y), gg = fmaxf(p1.x, 0.f), og = sigf(p1.y);
        cc = fg * cc + ig * gg;
        float hv = og * fmaxf(cc, 0.f);
        if (t == TT - 1) g_h2[(brow << 6) + j] = hv;
        float* hn = hd + (buf ^ 1) * 512;
        *(u64*)(hn + (j << 3) + (b << 1)) = pack2(hv, hv);
        __syncthreads();
        buf ^= 1;
    }
}

// ---------------------------------------------------------------------------
// Dense head
// ---------------------------------------------------------------------------
__global__ void dense_kernel(const float* __restrict__ Wd1, const float* __restrict__ bd1,
                             const float* __restrict__ Wd2, const float* __restrict__ bd2,
                             float* __restrict__ out)
{
    int b = blockIdx.x * blockDim.x + threadIdx.x;
    if (b >= BB) return;
    float h[H2];
#pragma unroll
    for (int k = 0; k < H2; k++) h[k] = g_h2[(b << 6) + k];
    float acc = bd2[0];
    for (int d = 0; d < 25; d++) {
        float s = bd1[d];
#pragma unroll
        for (int k = 0; k < H2; k++) s += h[k] * Wd1[k * 25 + d];
        acc += s * Wd2[d];
    }
    out[b] = acc;
}

// ---------------------------------------------------------------------------
// Launch
// ---------------------------------------------------------------------------
extern "C" void kernel_launch(void* const* d_in, const int* in_sizes, int n_in,
                              void* d_out, int out_size)
{
    const float* x   = (const float*)d_in[0];
    const float* W1  = (const float*)d_in[1];
    const float* U1  = (const float*)d_in[2];
    const float* b1  = (const float*)d_in[3];
    const float* W2  = (const float*)d_in[4];
    const float* U2  = (const float*)d_in[5];
    const float* b2  = (const float*)d_in[6];
    const float* Wd1 = (const float*)d_in[7];
    const float* bd1 = (const float*)d_in[8];
    const float* Wd2 = (const float*)d_in[9];
    const float* bd2 = (const float*)d_in[10];
    float* out = (float*)d_out;

    cudaFuncSetAttribute(gemm_kernel, cudaFuncAttributeMaxDynamicSharedMemorySize, GEMM_SMEM);
    cudaFuncSetAttribute(rec1_kernel, cudaFuncAttributeMaxDynamicSharedMemorySize, REC1_SMEM);
    cudaFuncSetAttribute(rec2_kernel, cudaFuncAttributeMaxDynamicSharedMemorySize, REC2_SMEM);

    float *pWp1, *pbp1, *pWp2, *pbp2, *pxw1, *pxw2, *ph1;
    cudaGetSymbolAddress((void**)&pWp1, g_Wp1);
    cudaGetSymbolAddress((void**)&pbp1, g_bp1);
    cudaGetSymbolAddress((void**)&pWp2, g_Wp2);
    cudaGetSymbolAddress((void**)&pbp2, g_bp2);
    cudaGetSymbolAddress((void**)&pxw1, g_xw1);
    cudaGetSymbolAddress((void**)&pxw2, g_xw2);
    cudaGetSymbolAddress((void**)&ph1,  g_h1);

    // 1. permute weights into gate-interleaved layout
    prep_kernel<<<256, 256>>>(W1, U1, b1, W2, U2, b2);

    // 2. xW1: x[b][t][:] @ Wp1 -> g_xw1[t][b][:]
    gemm_kernel<<<dim3((TT * BB) / 128, G1 / 128), 256, GEMM_SMEM>>>(
        x, pWp1, pbp1, pxw1, FF, TT * FF, FF, G1);

    // 3. layer-1 recurrence -> g_h1[t][b][:]
    rec1_kernel<<<BB / 4, 256, REC1_SMEM>>>();

    // 4. xW2: h1[t][b][:] @ Wp2 -> g_xw2[t][b][:]
    gemm_kernel<<<dim3((TT * BB) / 128, G2 / 128), 256, GEMM_SMEM>>>(
        ph1, pWp2, pbp2, pxw2, BB * H1, H1, H1, G2);

    // 5. layer-2 recurrence -> g_h2[b][:]
    rec2_kernel<<<BB / 4, 256, REC2_SMEM>>>();

    // 6. dense head
    dense_kernel<<<2, 256>>>(Wd1, bd1, Wd2, bd2, out);
}

// round 12
// speedup vs baseline: 1.4245x; 1.4245x over previous
#include <cuda_runtime.h>
#include <cuda_bf16.h>
#include <cstddef>
#include <cstdint>

// Problem constants
#define BB 512   // batch
#define TT 512   // timesteps
#define FF 64    // input features
#define H1 128   // layer1 hidden
#define G1 512   // 4*H1
#define H2 64    // layer2 hidden
#define G2 256   // 4*H2

typedef unsigned long long u64;

// ---------------------------------------------------------------------------
// Packed fp32x2 helpers
// ---------------------------------------------------------------------------
__device__ __forceinline__ u64 pack2(float lo, float hi) {
    u64 r; asm("mov.b64 %0, {%1, %2};" : "=l"(r) : "f"(lo), "f"(hi)); return r;
}
__device__ __forceinline__ float2 unpack2(u64 v) {
    float2 f; asm("mov.b64 {%0, %1}, %2;" : "=f"(f.x), "=f"(f.y) : "l"(v)); return f;
}
__device__ __forceinline__ void fma2(u64& d, u64 a, u64 b) {
    asm("fma.rn.f32x2 %0, %1, %2, %0;" : "+l"(d) : "l"(a), "l"(b));
}
__device__ __forceinline__ void add2(u64& d, u64 a) {
    asm("add.rn.f32x2 %0, %0, %1;" : "+l"(d) : "l"(a));
}

// ---------------------------------------------------------------------------
// Device scratch
// ---------------------------------------------------------------------------
__device__ float g_bp1[G1];
__device__ float g_Up1[H1 * G1];        // U1 permuted: [k][j*4+gate]
__device__ float g_bp2[G2];
__device__ float g_Up2[H2 * G2];
// Transposed stacked-K weights: [n][k'] with k' = [Wh | Wl | Wh]
__device__ __align__(16) __nv_bfloat16 g_Wt1[G1 * 3 * FF];   // [512][192]
__device__ __align__(16) __nv_bfloat16 g_Wt2[G2 * 3 * H1];   // [256][384]
__device__ float g_xw1[(size_t)TT * BB * G1];  // [t][b][j*4+gate]
__device__ float g_h1[(size_t)TT * BB * H1];   // [t][b][j]
__device__ float g_xw2[(size_t)TT * BB * G2];  // [t][b][j*4+gate]
__device__ float g_h2[BB * H2];                // final layer2 h

__device__ __forceinline__ float sigf(float x) {
    return __fdividef(1.0f, 1.0f + __expf(-x));
}

// ---------------------------------------------------------------------------
// Prep: permuted fp32 bias/U (n = j*4+gate, gate order i,f,g,o) + transposed
// stacked-K bf16 weights Wt[n][k'] with k' spans [Wh | Wl | Wh].
// ---------------------------------------------------------------------------
__global__ void prep_kernel(const float* __restrict__ W1, const float* __restrict__ U1,
                            const float* __restrict__ b1, const float* __restrict__ W2,
                            const float* __restrict__ U2, const float* __restrict__ b2)
{
    int i = blockIdx.x * blockDim.x + threadIdx.x;
    if (i < G1) {
        int j = i >> 2, gi = i & 3;
        g_bp1[i] = b1[gi * H1 + j];
    }
    if (i < H1 * G1) {
        int k = i >> 9, n = i & 511;
        int j = n >> 2, gi = n & 3;
        g_Up1[i] = U1[k * G1 + gi * H1 + j];
    }
    if (i < G2) {
        int j = i >> 2, gi = i & 3;
        g_bp2[i] = b2[gi * H2 + j];
    }
    if (i < H2 * G2) {
        int k = i >> 8, n = i & 255;
        int j = n >> 2, gi = n & 3;
        g_Up2[i] = U2[k * G2 + gi * H2 + j];
    }
    if (i < G1 * 3 * FF) {   // Wt1[n][kp], n in [0,512), kp in [0,192)
        int n = i / 192, kp = i - n * 192;
        int p = kp / FF, ks = kp - p * FF;
        float v = W1[ks * G1 + (n & 3) * H1 + (n >> 2)];
        __nv_bfloat16 h = __float2bfloat16(v);
        g_Wt1[i] = (p == 1) ? __float2bfloat16(v - __bfloat162float(h)) : h;
    }
    if (i < G2 * 3 * H1) {   // Wt2[n][kp], n in [0,256), kp in [0,384)
        int n = i / 384, kp = i - n * 384;
        int p = kp / H1, ks = kp - p * H1;
        float v = W2[ks * G2 + (n & 3) * H2 + (n >> 2)];
        __nv_bfloat16 h = __float2bfloat16(v);
        g_Wt2[i] = (p == 1) ? __float2bfloat16(v - __bfloat162float(h)) : h;
    }
}

// ---------------------------------------------------------------------------
// Tensor-core GEMM via mma.sync m16n8k16 bf16 (fp32 acc), stacked-K hi/lo.
// C[m][n] = sum_{k'} Acat[m][k'] * Wt[n][k'] + bias[n]
//   Acat = [Ah | Ah | Al] built on the fly from fp32 A.
// CTA 128(m) x 128(n), 256 thr = 8 warps (wm in {0,1} x wn in [0,4)),
// warp tile 64(m) x 32(n). NO ldmatrix: all fragments loaded as explicit
// u32 LDS per the documented PTX fragment layouts.
// smem: As[m=128][40 bf16] (80B stride), Bs[n=128][40 bf16].
// ---------------------------------------------------------------------------
#define GMMA_SMEM (128 * 80 + 128 * 80)   // 20480 B

__global__ __launch_bounds__(256, 2) void gemm_mma(
    const float* __restrict__ A, const __nv_bfloat16* __restrict__ Wt,
    const float* __restrict__ bias, float* __restrict__ C,
    int sT, int sB, int K, int Kcat, int Ntot)
{
    extern __shared__ char smb[];
    __nv_bfloat16* As = (__nv_bfloat16*)smb;            // [128][40]
    __nv_bfloat16* Bs = (__nv_bfloat16*)(smb + 10240);  // [128][40]
    const int tid = threadIdx.x, lane = tid & 31, wid = tid >> 5;
    const int wm = wid & 1, wn = wid >> 1;
    const int grp = lane >> 2;          // 0..7
    const int qc  = lane & 3;           // 0..3
    const int mt = blockIdx.x << 7, nt = blockIdx.y << 7;

    float acc[4][4][4];
#pragma unroll
    for (int mi = 0; mi < 4; mi++)
#pragma unroll
        for (int ni = 0; ni < 4; ni++)
#pragma unroll
            for (int q = 0; q < 4; q++) acc[mi][ni][q] = 0.f;

    // A loader: thread handles row r = tid>>1, 16-element k half hf = tid&1
    const int r = tid >> 1, hf = tid & 1;
    const int gm = mt + r;
    const int t0 = gm >> 9, b0 = gm & 511;
    const float* arow = A + (size_t)t0 * sT + (size_t)b0 * sB;

    const int nchunks = Kcat >> 5;
    for (int c = 0; c < nchunks; c++) {
        {   // ---- A: 16 fp32 -> bf16 (hi or lo half) ----
            int kbase = (c << 5) + (hf << 4);
            int lo = (kbase >= (K << 1));
            int ksrc = kbase; if (ksrc >= K) ksrc -= K; if (ksrc >= K) ksrc -= K;
            float4 v0 = *(const float4*)(arow + ksrc);
            float4 v1 = *(const float4*)(arow + ksrc + 4);
            float4 v2 = *(const float4*)(arow + ksrc + 8);
            float4 v3 = *(const float4*)(arow + ksrc + 12);
            float f[16] = {v0.x, v0.y, v0.z, v0.w, v1.x, v1.y, v1.z, v1.w,
                           v2.x, v2.y, v2.z, v2.w, v3.x, v3.y, v3.z, v3.w};
            unsigned o[8];
#pragma unroll
            for (int q = 0; q < 8; q++) {
                __nv_bfloat16 h0 = __float2bfloat16(f[2 * q]);
                __nv_bfloat16 h1 = __float2bfloat16(f[2 * q + 1]);
                if (lo) {
                    h0 = __float2bfloat16(f[2 * q] - __bfloat162float(h0));
                    h1 = __float2bfloat16(f[2 * q + 1] - __bfloat162float(h1));
                }
                o[q] = (unsigned)__bfloat16_as_ushort(h0) |
                       ((unsigned)__bfloat16_as_ushort(h1) << 16);
            }
            uint4* dst = (uint4*)((char*)As + r * 80 + hf * 32);
            dst[0] = make_uint4(o[0], o[1], o[2], o[3]);
            dst[1] = make_uint4(o[4], o[5], o[6], o[7]);
        }
        {   // ---- B: Wt[n][k'] slice, raw 16B copies (2 per thread) ----
            int n = tid >> 1, s0 = tid & 1;
            const __nv_bfloat16* src = Wt + (size_t)(nt + n) * Kcat + (c << 5);
#pragma unroll
            for (int s = 0; s < 2; s++) {
                int seg = s0 + (s << 1);   // 0..3, 8 elements each
                *(uint4*)((char*)Bs + n * 80 + seg * 16) =
                    *(const uint4*)(src + (seg << 3));
            }
        }
        __syncthreads();
#pragma unroll
        for (int ks = 0; ks < 2; ks++) {
            const int kofs = (ks << 4) + (qc << 1);   // k-lo element index
            // A fragments: a0={A[g][k],A[g][k+1]}, a1=row+8, a2=k+8, a3=both
            uint32_t af[4][4];
#pragma unroll
            for (int mi = 0; mi < 4; mi++) {
                const __nv_bfloat16* ar0 = As + (wm * 64 + mi * 16 + grp) * 40 + kofs;
                af[mi][0] = *(const uint32_t*)(ar0);
                af[mi][1] = *(const uint32_t*)(ar0 + 8 * 40);
                af[mi][2] = *(const uint32_t*)(ar0 + 8);
                af[mi][3] = *(const uint32_t*)(ar0 + 8 * 40 + 8);
            }
            // B fragments: b0={B[k][n],B[k+1][n]} = Bs[n][k..k+1], b1=k+8
            uint32_t bf[4][2];
#pragma unroll
            for (int ni = 0; ni < 4; ni++) {
                const __nv_bfloat16* br0 = Bs + (wn * 32 + ni * 8 + grp) * 40 + kofs;
                bf[ni][0] = *(const uint32_t*)(br0);
                bf[ni][1] = *(const uint32_t*)(br0 + 8);
            }
#pragma unroll
            for (int mi = 0; mi < 4; mi++)
#pragma unroll
                for (int ni = 0; ni < 4; ni++) {
                    asm volatile(
                        "mma.sync.aligned.m16n8k16.row.col.f32.bf16.bf16.f32 "
                        "{%0,%1,%2,%3}, {%4,%5,%6,%7}, {%8,%9}, {%0,%1,%2,%3};"
                        : "+f"(acc[mi][ni][0]), "+f"(acc[mi][ni][1]),
                          "+f"(acc[mi][ni][2]), "+f"(acc[mi][ni][3])
                        : "r"(af[mi][0]), "r"(af[mi][1]), "r"(af[mi][2]), "r"(af[mi][3]),
                          "r"(bf[ni][0]), "r"(bf[ni][1]));
                }
        }
        __syncthreads();
    }

    // ---- epilogue: canonical C fragment (c0,c1 @ row=grp, c2,c3 @ row+8) ----
#pragma unroll
    for (int mi = 0; mi < 4; mi++) {
        int r0 = mt + wm * 64 + mi * 16 + grp;
#pragma unroll
        for (int ni = 0; ni < 4; ni++) {
            int col = nt + wn * 32 + ni * 8 + (qc << 1);
            float b0v = __ldg(bias + col), b1v = __ldg(bias + col + 1);
            *(float2*)(C + (size_t)r0 * Ntot + col) =
                make_float2(acc[mi][ni][0] + b0v, acc[mi][ni][1] + b1v);
            *(float2*)(C + (size_t)(r0 + 8) * Ntot + col) =
                make_float2(acc[mi][ni][2] + b0v, acc[mi][ni][3] + b1v);
        }
    }
}

// ---------------------------------------------------------------------------
// Layer-1 recurrence (proven R4). 128 CTAs x 256 threads; CTA owns 4 batch
// rows. thread = (j, ks in {0,1}); ks splits K=128. Per ks-half: 32 U rows in
// smem, 32 in registers. h as dup pairs {h,h} in smem (broadcast reads).
// ---------------------------------------------------------------------------
#define REC1_SMEM ((64 * 512 + 2 * 128 * 8 + 128 * 20) * 4)  // 149504 B

__global__ __launch_bounds__(256, 1) void rec1_kernel()
{
    extern __shared__ float sm[];
    float* Us = sm;                  // [64][512]
    float* hd = sm + 64 * 512;       // [2][128][8]
    float* ex = hd + 2 * 128 * 8;    // [128][20]

    const int tid  = threadIdx.x;
    const int j    = tid & 127;
    const int ks   = tid >> 7;
    const int brow = blockIdx.x << 2;

    for (int i = tid; i < 64 * 128; i += 256) {
        int s = i >> 7;
        int c = (i & 127) << 2;
        int krow = (s < 32) ? s : (s + 32);
        *(float4*)(Us + s * 512 + c) = *(const float4*)(g_Up1 + krow * 512 + c);
    }
    const int rbase = ks * 64 + 32;
    ulonglong2 uw[32];
#pragma unroll
    for (int r = 0; r < 32; r++)
        uw[r] = *(const ulonglong2*)(g_Up1 + (rbase + r) * 512 + (j << 2));
    for (int i = tid; i < 2 * 128 * 8; i += 256) hd[i] = 0.f;
    float cc[4] = {0.f, 0.f, 0.f, 0.f};
    __syncthreads();

    const float* up0 = Us + (ks * 32) * 512 + (j << 2);
    int buf = 0;
    for (int t = 0; t < TT; t++) {
        u64 z2[4][2];
#pragma unroll
        for (int b = 0; b < 4; b++) { z2[b][0] = 0ull; z2[b][1] = 0ull; }

        ulonglong2 xv[4];
        if (ks == 0) {
#pragma unroll
            for (int b = 0; b < 4; b++)
                xv[b] = *(const ulonglong2*)(g_xw1 + ((size_t)(t * BB + brow + b) << 9) + (j << 2));
        }

        const float* hb = hd + buf * 1024;
        {
            const float* hp = hb + (ks * 64) * 8;
            const float* up = up0;
#pragma unroll 4
            for (int r = 0; r < 32; r++) {
                ulonglong2 hA = *(const ulonglong2*)(hp + (r << 3));
                ulonglong2 hB = *(const ulonglong2*)(hp + (r << 3) + 4);
                ulonglong2 uv = *(const ulonglong2*)(up);
                up += 512;
                fma2(z2[0][0], hA.x, uv.x); fma2(z2[0][1], hA.x, uv.y);
                fma2(z2[1][0], hA.y, uv.x); fma2(z2[1][1], hA.y, uv.y);
                fma2(z2[2][0], hB.x, uv.x); fma2(z2[2][1], hB.x, uv.y);
                fma2(z2[3][0], hB.y, uv.x); fma2(z2[3][1], hB.y, uv.y);
            }
        }
        {
            const float* hp = hb + rbase * 8;
#pragma unroll
            for (int r = 0; r < 32; r++) {
                ulonglong2 hA = *(const ulonglong2*)(hp + (r << 3));
                ulonglong2 hB = *(const ulonglong2*)(hp + (r << 3) + 4);
                fma2(z2[0][0], hA.x, uw[r].x); fma2(z2[0][1], hA.x, uw[r].y);
                fma2(z2[1][0], hA.y, uw[r].x); fma2(z2[1][1], hA.y, uw[r].y);
                fma2(z2[2][0], hB.x, uw[r].x); fma2(z2[2][1], hB.x, uw[r].y);
                fma2(z2[3][0], hB.y, uw[r].x); fma2(z2[3][1], hB.y, uw[r].y);
            }
        }
        if (ks) {
#pragma unroll
            for (int b = 0; b < 4; b++)
                *(ulonglong2*)(ex + j * 20 + (b << 2)) = make_ulonglong2(z2[b][0], z2[b][1]);
        }
        __syncthreads();
        if (ks == 0) {
            float* hn = hd + (buf ^ 1) * 1024;
            float hv[4];
#pragma unroll
            for (int b = 0; b < 4; b++) {
                ulonglong2 e = *(const ulonglong2*)(ex + j * 20 + (b << 2));
                add2(z2[b][0], e.x);
                add2(z2[b][1], e.y);
                add2(z2[b][0], xv[b].x);
                add2(z2[b][1], xv[b].y);
                float2 p0 = unpack2(z2[b][0]);
                float2 p1 = unpack2(z2[b][1]);
                float ig = sigf(p0.x);
                float fg = sigf(p0.y);
                float gg = fmaxf(p1.x, 0.f);
                float og = sigf(p1.y);
                cc[b] = fg * cc[b] + ig * gg;
                hv[b] = og * fmaxf(cc[b], 0.f);
                g_h1[((size_t)(t * BB + brow + b) << 7) + j] = hv[b];
            }
            *(ulonglong2*)(hn + (j << 3)) =
                make_ulonglong2(pack2(hv[0], hv[0]), pack2(hv[1], hv[1]));
            *(ulonglong2*)(hn + (j << 3) + 4) =
                make_ulonglong2(pack2(hv[2], hv[2]), pack2(hv[3], hv[3]));
        }
        __syncthreads();
        buf ^= 1;
    }
}

// ---------------------------------------------------------------------------
// Layer-2 recurrence (proven R4), 4-way k-split. 128 CTAs x 256 threads.
// ---------------------------------------------------------------------------
#define REC2_SMEM ((32 * 256 + 2 * 64 * 8 + 3 * 64 * 20) * 4)  // 52480 B

__global__ __launch_bounds__(256, 1) void rec2_kernel()
{
    extern __shared__ float sm[];
    float* Us = sm;                  // [32][256]
    float* hd = sm + 32 * 256;       // [2][64][8]
    float* ex = hd + 2 * 64 * 8;     // [3][64][20]

    const int tid  = threadIdx.x;
    const int j    = tid & 63;
    const int ks   = tid >> 6;
    const int brow = blockIdx.x << 2;

    for (int i = tid; i < 32 * 64; i += 256) {
        int s = i >> 6;
        int c = (i & 63) << 2;
        int krow = ((s >> 3) << 4) + (s & 7);
        *(float4*)(Us + s * 256 + c) = *(const float4*)(g_Up2 + krow * 256 + c);
    }
    const int rbase = (ks << 4) + 8;
    ulonglong2 uw[8];
#pragma unroll
    for (int r = 0; r < 8; r++)
        uw[r] = *(const ulonglong2*)(g_Up2 + (rbase + r) * 256 + (j << 2));
    for (int i = tid; i < 2 * 64 * 8; i += 256) hd[i] = 0.f;
    float cc[4] = {0.f, 0.f, 0.f, 0.f};
    __syncthreads();

    const float* up0 = Us + (ks << 3) * 256 + (j << 2);
    int buf = 0;
    for (int t = 0; t < TT; t++) {
        u64 z2[4][2];
#pragma unroll
        for (int b = 0; b < 4; b++) { z2[b][0] = 0ull; z2[b][1] = 0ull; }

        ulonglong2 xv[4];
        if (ks == 0) {
#pragma unroll
            for (int b = 0; b < 4; b++)
                xv[b] = *(const ulonglong2*)(g_xw2 + ((size_t)(t * BB + brow + b) << 8) + (j << 2));
        }
        const float* hb = hd + buf * 512;
        {
            const float* hp = hb + (ks << 4) * 8;
            const float* up = up0;
#pragma unroll
            for (int r = 0; r < 8; r++) {
                ulonglong2 hA = *(const ulonglong2*)(hp + (r << 3));
                ulonglong2 hB = *(const ulonglong2*)(hp + (r << 3) + 4);
                ulonglong2 uv = *(const ulonglong2*)(up);
                up += 256;
                fma2(z2[0][0], hA.x, uv.x); fma2(z2[0][1], hA.x, uv.y);
                fma2(z2[1][0], hA.y, uv.x); fma2(z2[1][1], hA.y, uv.y);
                fma2(z2[2][0], hB.x, uv.x); fma2(z2[2][1], hB.x, uv.y);
                fma2(z2[3][0], hB.y, uv.x); fma2(z2[3][1], hB.y, uv.y);
            }
        }
        {
            const float* hp = hb + rbase * 8;
#pragma unroll
            for (int r = 0; r < 8; r++) {
                ulonglong2 hA = *(const ulonglong2*)(hp + (r << 3));
                ulonglong2 hB = *(const ulonglong2*)(hp + (r << 3) + 4);
                fma2(z2[0][0], hA.x, uw[r].x); fma2(z2[0][1], hA.x, uw[r].y);
                fma2(z2[1][0], hA.y, uw[r].x); fma2(z2[1][1], hA.y, uw[r].y);
                fma2(z2[2][0], hB.x, uw[r].x); fma2(z2[2][1], hB.x, uw[r].y);
                fma2(z2[3][0], hB.y, uw[r].x); fma2(z2[3][1], hB.y, uw[r].y);
            }
        }
        if (ks) {
            float* exq = ex + (ks - 1) * 1280 + j * 20;
#pragma unroll
            for (int b = 0; b < 4; b++)
                *(ulonglong2*)(exq + (b << 2)) = make_ulonglong2(z2[b][0], z2[b][1]);
        }
        __syncthreads();
        if (ks == 0) {
            float* hn = hd + (buf ^ 1) * 512;
            float hv[4];
#pragma unroll
            for (int b = 0; b < 4; b++) {
#pragma unroll
                for (int q = 0; q < 3; q++) {
                    ulonglong2 e = *(const ulonglong2*)(ex + q * 1280 + j * 20 + (b << 2));
                    add2(z2[b][0], e.x);
                    add2(z2[b][1], e.y);
                }
                add2(z2[b][0], xv[b].x);
                add2(z2[b][1], xv[b].y);
                float2 p0 = unpack2(z2[b][0]);
                float2 p1 = unpack2(z2[b][1]);
                float ig = sigf(p0.x);
                float fg = sigf(p0.y);
                float gg = fmaxf(p1.x, 0.f);
                float og = sigf(p1.y);
                cc[b] = fg * cc[b] + ig * gg;
                hv[b] = og * fmaxf(cc[b], 0.f);
                if (t == TT - 1)
                    g_h2[((brow + b) << 6) + j] = hv[b];
            }
            *(ulonglong2*)(hn + (j << 3)) =
                make_ulonglong2(pack2(hv[0], hv[0]), pack2(hv[1], hv[1]));
            *(ulonglong2*)(hn + (j << 3) + 4) =
                make_ulonglong2(pack2(hv[2], hv[2]), pack2(hv[3], hv[3]));
        }
        __syncthreads();
        buf ^= 1;
    }
}

// ---------------------------------------------------------------------------
// Dense head
// ---------------------------------------------------------------------------
__global__ void dense_kernel(const float* __restrict__ Wd1, const float* __restrict__ bd1,
                             const float* __restrict__ Wd2, const float* __restrict__ bd2,
                             float* __restrict__ out)
{
    int b = blockIdx.x * blockDim.x + threadIdx.x;
    if (b >= BB) return;
    float h[H2];
#pragma unroll
    for (int k = 0; k < H2; k++) h[k] = g_h2[(b << 6) + k];
    float acc = bd2[0];
    for (int d = 0; d < 25; d++) {
        float s = bd1[d];
#pragma unroll
        for (int k = 0; k < H2; k++) s += h[k] * Wd1[k * 25 + d];
        acc += s * Wd2[d];
    }
    out[b] = acc;
}

// ---------------------------------------------------------------------------
// Launch
// ---------------------------------------------------------------------------
extern "C" void kernel_launch(void* const* d_in, const int* in_sizes, int n_in,
                              void* d_out, int out_size)
{
    const float* x   = (const float*)d_in[0];
    const float* W1  = (const float*)d_in[1];
    const float* U1  = (const float*)d_in[2];
    const float* b1  = (const float*)d_in[3];
    const float* W2  = (const float*)d_in[4];
    const float* U2  = (const float*)d_in[5];
    const float* b2  = (const float*)d_in[6];
    const float* Wd1 = (const float*)d_in[7];
    const float* bd1 = (const float*)d_in[8];
    const float* Wd2 = (const float*)d_in[9];
    const float* bd2 = (const float*)d_in[10];
    float* out = (float*)d_out;

    cudaFuncSetAttribute(rec1_kernel, cudaFuncAttributeMaxDynamicSharedMemorySize, REC1_SMEM);
    cudaFuncSetAttribute(rec2_kernel, cudaFuncAttributeMaxDynamicSharedMemorySize, REC2_SMEM);

    float *pbp1, *pbp2, *pxw1, *pxw2, *ph1;
    void *pWt1, *pWt2;
    cudaGetSymbolAddress((void**)&pbp1, g_bp1);
    cudaGetSymbolAddress((void**)&pbp2, g_bp2);
    cudaGetSymbolAddress((void**)&pxw1, g_xw1);
    cudaGetSymbolAddress((void**)&pxw2, g_xw2);
    cudaGetSymbolAddress((void**)&ph1,  g_h1);
    cudaGetSymbolAddress(&pWt1, g_Wt1);
    cudaGetSymbolAddress(&pWt2, g_Wt2);

    // 1. weight permute + transposed stacked-K bf16 images
    prep_kernel<<<512, 256>>>(W1, U1, b1, W2, U2, b2);

    // 2. xW1 (tensor cores): x @ W1 -> g_xw1[t][b][:]   (Kcat = 192)
    gemm_mma<<<dim3((TT * BB) / 128, G1 / 128), 256, GMMA_SMEM>>>(
        x, (const __nv_bfloat16*)pWt1, pbp1, pxw1, FF, TT * FF, FF, 3 * FF, G1);

    // 3. layer-1 recurrence -> g_h1[t][b][:]
    rec1_kernel<<<BB / 4, 256, REC1_SMEM>>>();

    // 4. xW2 (tensor cores): h1 @ W2 -> g_xw2[t][b][:]  (Kcat = 384)
    gemm_mma<<<dim3((TT * BB) / 128, G2 / 128), 256, GMMA_SMEM>>>(
        ph1, (const __nv_bfloat16*)pWt2, pbp2, pxw2, BB * H1, H1, H1, 3 * H1, G2);

    // 5. layer-2 recurrence -> g_h2[b][:]
    rec2_kernel<<<BB / 4, 256, REC2_SMEM>>>();

    // 6. dense head
    dense_kernel<<<2, 256>>>(Wd1, bd1, Wd2, bd2, out);
}